// round 14
// baseline (speedup 1.0000x reference)
#include <cuda_runtime.h>
#include <math.h>

constexpr int B = 8, H = 32, D = 128, T = 64, P = 64, SEL = 32, NSPLIT = 4;
constexpr float SM_SCALE = 0.08838834764831845f; // 1/sqrt(128)

// Scratch (allocation-free: __device__ globals)
__device__ float g_qr[B * H * D];            // RoPE'd q
__device__ float g_sraw[B * H * P * T];      // per-token raw logits (qr . k_int)
__device__ float g_pscore[B * H * P];        // page scores
__device__ float g_w[B * H * SEL * T];       // unnormalized softmax weights
__device__ int   g_selphys[B * H * SEL];     // selected physical pages (ascending)
__device__ float g_recip[B * H];             // v_scale / Z
__device__ float g_partial[B * H * NSPLIT * D];

// PDL primitives: wait for predecessor's data; signal dependents may launch.
__device__ __forceinline__ void gdc_wait()   { asm volatile("griddepcontrol.wait;" ::: "memory"); }
__device__ __forceinline__ void gdc_launch() { asm volatile("griddepcontrol.launch_dependents;" ::: "memory"); }

// ---------------------------------------------------------------------------
// Kernel 1: NeoX RoPE on q at pos = seq_len-1. Double-precision trig to match
// jax f32 cos/sin for angles up to ~4095 rad.
// ---------------------------------------------------------------------------
__global__ void rope_kernel(const float* __restrict__ q,
                            const int* __restrict__ seq_lens)
{
    int h = blockIdx.x, b = blockIdx.y;
    int i = threadIdx.x;                      // 0..63 (half dim)
    int pos = seq_lens[b] - 1;
    float x = (float)(2 * i) / 128.0f;
    float inv = (float)(1.0 / pow(10000.0, (double)x));
    float ang = (float)pos * inv;             // f32 product, like reference
    float c = (float)cos((double)ang);
    float s = (float)sin((double)ang);
    const float* qb = q + (b * H + h) * D;
    float q1 = qb[i], q2 = qb[i + 64];
    float* o = g_qr + (b * H + h) * D;
    o[i]      = q1 * c - q2 * s;
    o[i + 64] = q2 * c + q1 * s;
    gdc_launch();
}

// ---------------------------------------------------------------------------
// Kernel 2: one streaming pass over K (valid pages only), one page per block,
// __launch_bounds__(256, 8), __ldcs on K / __stcs on s_raw (R10 winner).
// Per-token logits s_raw = qr.k_int AND page score via EXACT integer column
// sums (matches reference mean-then-dot ordering).
// ---------------------------------------------------------------------------
__global__ void __launch_bounds__(256, 8)
score_kernel(const int* __restrict__ k_cache,
             const int* __restrict__ block_table,
             const int* __restrict__ seq_lens,
             const float* __restrict__ k_scale)
{
    int p = blockIdx.x, h = blockIdx.y, b = blockIdx.z;
    int bh = b * H + h;
    int seq = seq_lens[b];                    // input: independent of rope
    int nvalid = (seq + T - 1) / T;
    if (p >= nvalid) {
        gdc_wait();
        if (threadIdx.x == 0) g_pscore[bh * P + p] = -INFINITY;
        gdc_launch();
        return;
    }
    int tid = threadIdx.x, lane = tid & 31, wid = tid >> 5;
    int phys = block_table[b * P + p];        // input: independent
    const int4* kb = reinterpret_cast<const int4*>(k_cache)
                     + ((phys * H + h) * T) * (D / 4);
    gdc_wait();                               // rope's g_qr now visible
    float4 q4 = reinterpret_cast<const float4*>(g_qr + bh * D)[lane];
    float* srow = g_sraw + (bh * P + p) * T;

    __shared__ float part[T][33];             // padded: conflict-free phase 2
    __shared__ int   ksum[8][D];
    __shared__ float wsum[4];

    // Warp w handles token rows w, w+8, ..., w+56 (coalesced).
    int s0 = 0, s1 = 0, s2 = 0, s3 = 0;
#pragma unroll
    for (int k = 0; k < 8; k++) {
        int4 v = __ldcs(&kb[(wid + k * 8) * (D / 4) + lane]);
        s0 += v.x; s1 += v.y; s2 += v.z; s3 += v.w;
        part[wid + k * 8][lane] =
            q4.x * (float)v.x + q4.y * (float)v.y
          + q4.z * (float)v.z + q4.w * (float)v.w;
    }
    ksum[wid][lane * 4 + 0] = s0;
    ksum[wid][lane * 4 + 1] = s1;
    ksum[wid][lane * 4 + 2] = s2;
    ksum[wid][lane * 4 + 3] = s3;
    __syncthreads();

    // Phase 2a: per-token dot reduce. 4 threads/row: 8 adds + 2 shfl.
    {
        int row = tid >> 2, qq = tid & 3;
        float v = 0.f;
#pragma unroll
        for (int j = 0; j < 8; j++) v += part[row][qq * 8 + j];
        v += __shfl_xor_sync(0xffffffffu, v, 1);
        v += __shfl_xor_sync(0xffffffffu, v, 2);
        if (qq == 0) __stcs(&srow[row], v);
    }

    // Phase 2b: page score from exact integer column sums.
    if (tid < D) {
        int s = 0;
#pragma unroll
        for (int w = 0; w < 8; w++) s += ksum[w][tid];
        float val = ((float)s * (1.0f / T)) * k_scale[0] * g_qr[bh * D + tid];
#pragma unroll
        for (int o = 16; o; o >>= 1) val += __shfl_xor_sync(0xffffffffu, val, o);
        if (lane == 0) wsum[wid] = val;
    }
    __syncthreads();
    if (tid == 0)
        g_pscore[bh * P + p] = wsum[0] + wsum[1] + wsum[2] + wsum[3];
    gdc_launch();
}

// ---------------------------------------------------------------------------
// Kernel 3: per (b,h): exact top-SEL selection (rank-based, jax tie-breaking)
// with slots assigned in ASCENDING PAGE ORDER (same set, physically monotonic
// iteration for vaccum's V gather), then 2-pass softmax over the 2048
// selected logits (token-masked). Weight slots use the same ordering, so the
// w <-> page pairing is exact; only fp summation order changes (deterministic).
// ---------------------------------------------------------------------------
__global__ void select_kernel(const int* __restrict__ block_table,
                              const int* __restrict__ seq_lens,
                              const float* __restrict__ k_scale,
                              const float* __restrict__ v_scale)
{
    int bh = blockIdx.x;
    int b = bh / H;
    int tid = threadIdx.x, lane = tid & 31, wid = tid >> 5;
    int seq = seq_lens[b];                    // input: independent

    __shared__ float sc[P];
    __shared__ int flag[P];                   // selected?
    __shared__ int selp[SEL];                 // pages, ascending
    __shared__ float sw[SEL * T];
    __shared__ float red[8];

    gdc_wait();                               // score's outputs now visible
    if (tid < P) sc[tid] = g_pscore[bh * P + tid];
    __syncthreads();
    int rank = SEL;
    if (tid < P) {
        float my = sc[tid];
        rank = 0;
#pragma unroll
        for (int j = 0; j < P; j++) {
            float o = sc[j];
            rank += (o > my) || (o == my && j < tid);
        }
        flag[tid] = (rank < SEL);
    }
    __syncthreads();
    if (tid < P && rank < SEL) {
        int slot = 0;                         // ascending-page slot
        for (int j = 0; j < tid; j++) slot += flag[j];
        selp[slot] = tid;
        g_selphys[bh * SEL + slot] = block_table[b * P + tid];
    }
    __syncthreads();

    float scale = k_scale[0] * SM_SCALE;
    float lmax = -INFINITY;
#pragma unroll
    for (int k = 0; k < 8; k++) {
        int e = tid + k * 256;
        int s = e >> 6, t = e & 63;
        int p = selp[s];
        float v = -INFINITY;
        if (p * T + t < seq) v = g_sraw[(bh * P + p) * T + t] * scale;
        sw[e] = v;
        lmax = fmaxf(lmax, v);
    }
#pragma unroll
    for (int o = 16; o; o >>= 1) lmax = fmaxf(lmax, __shfl_xor_sync(0xffffffffu, lmax, o));
    if (lane == 0) red[wid] = lmax;
    __syncthreads();
    float m = fmaxf(fmaxf(fmaxf(red[0], red[1]), fmaxf(red[2], red[3])),
                    fmaxf(fmaxf(red[4], red[5]), fmaxf(red[6], red[7])));
    __syncthreads();

    float lsum = 0.f;
#pragma unroll
    for (int k = 0; k < 8; k++) {
        int e = tid + k * 256;
        float ee = expf(sw[e] - m);           // expf(-inf - m) = 0 for masked
        g_w[bh * (SEL * T) + e] = ee;
        lsum += ee;
    }
#pragma unroll
    for (int o = 16; o; o >>= 1) lsum += __shfl_xor_sync(0xffffffffu, lsum, o);
    if (lane == 0) red[wid] = lsum;
    __syncthreads();
    if (tid == 0) {
        float Z = red[0] + red[1] + red[2] + red[3]
                + red[4] + red[5] + red[6] + red[7];
        g_recip[bh] = v_scale[0] / Z;
    }
    gdc_launch();
}

// ---------------------------------------------------------------------------
// Kernel 4: V accumulation (R10 winner; pages now arrive in ascending
// physical order -> monotonic DRAM walk). __ldcs on V, __stcs on partials.
// ---------------------------------------------------------------------------
__global__ void vaccum_kernel(const int* __restrict__ v_cache)
{
    int split = blockIdx.x, h = blockIdx.y, b = blockIdx.z;
    int bh = b * H + h;
    int tid = threadIdx.x, lane = tid & 31, wid = tid >> 5;
    const float* wb = g_w + bh * (SEL * T);
    const int* physb = g_selphys + bh * SEL;
    gdc_wait();                               // select's outputs now visible

    float a0 = 0, a1 = 0, a2 = 0, a3 = 0;
#pragma unroll
    for (int si = 0; si < SEL / NSPLIT; si++) {
        int s = split * (SEL / NSPLIT) + si;
        int phys = physb[s];
        const int4* vb = reinterpret_cast<const int4*>(v_cache)
                         + ((phys * H + h) * T) * (D / 4);
        float ww[8];
        int4 vv[8];
#pragma unroll
        for (int k = 0; k < 8; k++) ww[k] = wb[s * T + wid + k * 8];
#pragma unroll
        for (int k = 0; k < 8; k++)
            vv[k] = __ldcs(&vb[(wid + k * 8) * (D / 4) + lane]);
#pragma unroll
        for (int k = 0; k < 8; k++) {
            float w = ww[k];
            a0 += w * (float)vv[k].x; a1 += w * (float)vv[k].y;
            a2 += w * (float)vv[k].z; a3 += w * (float)vv[k].w;
        }
    }

    __shared__ float red[8][D];
    red[wid][lane * 4 + 0] = a0;
    red[wid][lane * 4 + 1] = a1;
    red[wid][lane * 4 + 2] = a2;
    red[wid][lane * 4 + 3] = a3;
    __syncthreads();
    if (tid < D) {
        float s = 0;
#pragma unroll
        for (int w = 0; w < 8; w++) s += red[w][tid];
        __stcs(&g_partial[(bh * NSPLIT + split) * D + tid], s);
    }
    gdc_launch();
}

// ---------------------------------------------------------------------------
// Kernel 5: combine partials, normalize, write out.
// ---------------------------------------------------------------------------
__global__ void combine_kernel(float* __restrict__ out)
{
    int bh = blockIdx.x;
    int d = threadIdx.x;
    gdc_wait();                               // vaccum partials now visible
    float r = g_recip[bh];
    float s = 0;
#pragma unroll
    for (int sp = 0; sp < NSPLIT; sp++)
        s += g_partial[(bh * NSPLIT + sp) * D + d];
    out[bh * D + d] = s * r;
}

// ---------------------------------------------------------------------------
// Host: PDL chain (R9 winner).
// ---------------------------------------------------------------------------
template <typename... Args>
static void launch_pdl(void (*kern)(Args...), dim3 grid, dim3 block, Args... args)
{
    cudaLaunchConfig_t cfg = {};
    cfg.gridDim = grid;
    cfg.blockDim = block;
    cfg.dynamicSmemBytes = 0;
    cfg.stream = 0;
    cudaLaunchAttribute attr[1];
    attr[0].id = cudaLaunchAttributeProgrammaticStreamSerialization;
    attr[0].val.programmaticStreamSerializationAllowed = 1;
    cfg.attrs = attr;
    cfg.numAttrs = 1;
    cudaLaunchKernelEx(&cfg, kern, args...);
}

extern "C" void kernel_launch(void* const* d_in, const int* in_sizes, int n_in,
                              void* d_out, int out_size)
{
    const float* q           = (const float*)d_in[0];
    const int*   k_cache     = (const int*)d_in[1];
    const int*   v_cache     = (const int*)d_in[2];
    const int*   block_table = (const int*)d_in[3];
    const int*   seq_lens    = (const int*)d_in[4];
    const float* k_scale     = (const float*)d_in[5];
    const float* v_scale     = (const float*)d_in[6];
    float* out = (float*)d_out;

    rope_kernel<<<dim3(H, B), 64>>>(q, seq_lens);
    launch_pdl(score_kernel, dim3(P, H, B), dim3(256),
               k_cache, block_table, seq_lens, k_scale);
    launch_pdl(select_kernel, dim3(B * H), dim3(256),
               block_table, seq_lens, k_scale, v_scale);
    launch_pdl(vaccum_kernel, dim3(NSPLIT, H, B), dim3(256), v_cache);
    launch_pdl(combine_kernel, dim3(B * H), dim3(D), out);
}

// round 15
// speedup vs baseline: 1.0454x; 1.0454x over previous
#include <cuda_runtime.h>
#include <math.h>

constexpr int B = 8, H = 32, D = 128, T = 64, P = 64, SEL = 32, NSPLIT = 4;
constexpr float SM_SCALE = 0.08838834764831845f; // 1/sqrt(128)

// Scratch (allocation-free: __device__ globals)
__device__ float g_qr[B * H * D];            // RoPE'd q
__device__ float g_sraw[B * H * P * T];      // per-token raw logits (qr . k_int)
__device__ float g_pscore[B * H * P];        // page scores
__device__ float g_w[B * H * SEL * T];       // unnormalized softmax weights
__device__ int   g_selphys[B * H * SEL];     // selected physical pages
__device__ float g_recip[B * H];             // v_scale / Z
__device__ float g_partial[B * H * NSPLIT * D];

// PDL primitives: wait for predecessor's data; signal dependents may launch.
__device__ __forceinline__ void gdc_wait()   { asm volatile("griddepcontrol.wait;" ::: "memory"); }
__device__ __forceinline__ void gdc_launch() { asm volatile("griddepcontrol.launch_dependents;" ::: "memory"); }

// ---------------------------------------------------------------------------
// Kernel 1: NeoX RoPE on q at pos = seq_len-1. Double-precision trig to match
// jax f32 cos/sin for angles up to ~4095 rad.
// ---------------------------------------------------------------------------
__global__ void rope_kernel(const float* __restrict__ q,
                            const int* __restrict__ seq_lens)
{
    int h = blockIdx.x, b = blockIdx.y;
    int i = threadIdx.x;                      // 0..63 (half dim)
    int pos = seq_lens[b] - 1;
    float x = (float)(2 * i) / 128.0f;
    float inv = (float)(1.0 / pow(10000.0, (double)x));
    float ang = (float)pos * inv;             // f32 product, like reference
    float c = (float)cos((double)ang);
    float s = (float)sin((double)ang);
    const float* qb = q + (b * H + h) * D;
    float q1 = qb[i], q2 = qb[i + 64];
    float* o = g_qr + (b * H + h) * D;
    o[i]      = q1 * c - q2 * s;
    o[i + 64] = q2 * c + q1 * s;
    gdc_launch();
}

// ---------------------------------------------------------------------------
// Kernel 2: one streaming pass over K (valid pages only), one page per block,
// __launch_bounds__(256, 8). K loads use __ldcs (read-once, evict-first) so
// the 400MB stream doesn't thrash L2; s_raw stores use __stcs. Per-token
// logits s_raw = qr.k_int AND page score via EXACT integer column sums
// (matches reference mean-then-dot ordering).
// ---------------------------------------------------------------------------
__global__ void __launch_bounds__(256, 8)
score_kernel(const int* __restrict__ k_cache,
             const int* __restrict__ block_table,
             const int* __restrict__ seq_lens,
             const float* __restrict__ k_scale)
{
    int p = blockIdx.x, h = blockIdx.y, b = blockIdx.z;
    int bh = b * H + h;
    int seq = seq_lens[b];                    // input: independent of rope
    int nvalid = (seq + T - 1) / T;
    if (p >= nvalid) {
        gdc_wait();
        if (threadIdx.x == 0) g_pscore[bh * P + p] = -INFINITY;
        gdc_launch();
        return;
    }
    int tid = threadIdx.x, lane = tid & 31, wid = tid >> 5;
    int phys = block_table[b * P + p];        // input: independent
    const int4* kb = reinterpret_cast<const int4*>(k_cache)
                     + ((phys * H + h) * T) * (D / 4);
    gdc_wait();                               // rope's g_qr now visible
    float4 q4 = reinterpret_cast<const float4*>(g_qr + bh * D)[lane];
    float* srow = g_sraw + (bh * P + p) * T;

    __shared__ float part[T][33];             // padded: conflict-free phase 2
    __shared__ int   ksum[8][D];
    __shared__ float wsum[4];

    // Warp w handles token rows w, w+8, ..., w+56 (coalesced).
    int s0 = 0, s1 = 0, s2 = 0, s3 = 0;
#pragma unroll
    for (int k = 0; k < 8; k++) {
        int4 v = __ldcs(&kb[(wid + k * 8) * (D / 4) + lane]);
        s0 += v.x; s1 += v.y; s2 += v.z; s3 += v.w;
        part[wid + k * 8][lane] =
            q4.x * (float)v.x + q4.y * (float)v.y
          + q4.z * (float)v.z + q4.w * (float)v.w;
    }
    ksum[wid][lane * 4 + 0] = s0;
    ksum[wid][lane * 4 + 1] = s1;
    ksum[wid][lane * 4 + 2] = s2;
    ksum[wid][lane * 4 + 3] = s3;
    __syncthreads();

    // Phase 2a: per-token dot reduce. 4 threads/row: 8 adds + 2 shfl.
    {
        int row = tid >> 2, qq = tid & 3;
        float v = 0.f;
#pragma unroll
        for (int j = 0; j < 8; j++) v += part[row][qq * 8 + j];
        v += __shfl_xor_sync(0xffffffffu, v, 1);
        v += __shfl_xor_sync(0xffffffffu, v, 2);
        if (qq == 0) __stcs(&srow[row], v);
    }

    // Phase 2b: page score from exact integer column sums.
    if (tid < D) {
        int s = 0;
#pragma unroll
        for (int w = 0; w < 8; w++) s += ksum[w][tid];
        float val = ((float)s * (1.0f / T)) * k_scale[0] * g_qr[bh * D + tid];
#pragma unroll
        for (int o = 16; o; o >>= 1) val += __shfl_xor_sync(0xffffffffu, val, o);
        if (lane == 0) wsum[wid] = val;
    }
    __syncthreads();
    if (tid == 0)
        g_pscore[bh * P + p] = wsum[0] + wsum[1] + wsum[2] + wsum[3];
    gdc_launch();
}

// ---------------------------------------------------------------------------
// Kernel 3: per (b,h): exact top-SEL selection (rank-based, jax tie-breaking),
// then 2-pass softmax over the 2048 selected logits (token-masked).
// ---------------------------------------------------------------------------
__global__ void select_kernel(const int* __restrict__ block_table,
                              const int* __restrict__ seq_lens,
                              const float* __restrict__ k_scale,
                              const float* __restrict__ v_scale)
{
    int bh = blockIdx.x;
    int b = bh / H;
    int tid = threadIdx.x, lane = tid & 31, wid = tid >> 5;
    int seq = seq_lens[b];                    // input: independent

    __shared__ float sc[P];
    __shared__ int selp[SEL];
    __shared__ float sw[SEL * T];
    __shared__ float red[8];

    gdc_wait();                               // score's outputs now visible
    if (tid < P) sc[tid] = g_pscore[bh * P + tid];
    __syncthreads();
    if (tid < P) {
        float my = sc[tid];
        int rank = 0;
#pragma unroll
        for (int j = 0; j < P; j++) {
            float o = sc[j];
            rank += (o > my) || (o == my && j < tid);
        }
        if (rank < SEL) {                     // exactly SEL selected (total order)
            selp[rank] = tid;
            g_selphys[bh * SEL + rank] = block_table[b * P + tid];
        }
    }
    __syncthreads();

    float scale = k_scale[0] * SM_SCALE;
    float lmax = -INFINITY;
#pragma unroll
    for (int k = 0; k < 8; k++) {
        int e = tid + k * 256;
        int s = e >> 6, t = e & 63;
        int p = selp[s];
        float v = -INFINITY;
        if (p * T + t < seq) v = g_sraw[(bh * P + p) * T + t] * scale;
        sw[e] = v;
        lmax = fmaxf(lmax, v);
    }
#pragma unroll
    for (int o = 16; o; o >>= 1) lmax = fmaxf(lmax, __shfl_xor_sync(0xffffffffu, lmax, o));
    if (lane == 0) red[wid] = lmax;
    __syncthreads();
    float m = fmaxf(fmaxf(fmaxf(red[0], red[1]), fmaxf(red[2], red[3])),
                    fmaxf(fmaxf(red[4], red[5]), fmaxf(red[6], red[7])));
    __syncthreads();

    float lsum = 0.f;
#pragma unroll
    for (int k = 0; k < 8; k++) {
        int e = tid + k * 256;
        float ee = expf(sw[e] - m);           // expf(-inf - m) = 0 for masked
        g_w[bh * (SEL * T) + e] = ee;
        lsum += ee;
    }
#pragma unroll
    for (int o = 16; o; o >>= 1) lsum += __shfl_xor_sync(0xffffffffu, lsum, o);
    if (lane == 0) red[wid] = lsum;
    __syncthreads();
    if (tid == 0) {
        float Z = red[0] + red[1] + red[2] + red[3]
                + red[4] + red[5] + red[6] + red[7];
        g_recip[bh] = v_scale[0] / Z;
    }
    gdc_launch();
}

// ---------------------------------------------------------------------------
// Kernel 4: V accumulation (R4 streaming body + __ldcs on V gather).
// 4-way page split per (b,h); deterministic partials via __stcs.
// ---------------------------------------------------------------------------
__global__ void vaccum_kernel(const int* __restrict__ v_cache)
{
    int split = blockIdx.x, h = blockIdx.y, b = blockIdx.z;
    int bh = b * H + h;
    int tid = threadIdx.x, lane = tid & 31, wid = tid >> 5;
    const float* wb = g_w + bh * (SEL * T);
    const int* physb = g_selphys + bh * SEL;
    gdc_wait();                               // select's outputs now visible

    float a0 = 0, a1 = 0, a2 = 0, a3 = 0;
#pragma unroll
    for (int si = 0; si < SEL / NSPLIT; si++) {
        int s = split * (SEL / NSPLIT) + si;
        int phys = physb[s];
        const int4* vb = reinterpret_cast<const int4*>(v_cache)
                         + ((phys * H + h) * T) * (D / 4);
        float ww[8];
        int4 vv[8];
#pragma unroll
        for (int k = 0; k < 8; k++) ww[k] = wb[s * T + wid + k * 8];
#pragma unroll
        for (int k = 0; k < 8; k++)
            vv[k] = __ldcs(&vb[(wid + k * 8) * (D / 4) + lane]);
#pragma unroll
        for (int k = 0; k < 8; k++) {
            float w = ww[k];
            a0 += w * (float)vv[k].x; a1 += w * (float)vv[k].y;
            a2 += w * (float)vv[k].z; a3 += w * (float)vv[k].w;
        }
    }

    __shared__ float red[8][D];
    red[wid][lane * 4 + 0] = a0;
    red[wid][lane * 4 + 1] = a1;
    red[wid][lane * 4 + 2] = a2;
    red[wid][lane * 4 + 3] = a3;
    __syncthreads();
    if (tid < D) {
        float s = 0;
#pragma unroll
        for (int w = 0; w < 8; w++) s += red[w][tid];
        __stcs(&g_partial[(bh * NSPLIT + split) * D + tid], s);
    }
    gdc_launch();
}

// ---------------------------------------------------------------------------
// Kernel 5: combine partials, normalize, write out.
// ---------------------------------------------------------------------------
__global__ void combine_kernel(float* __restrict__ out)
{
    int bh = blockIdx.x;
    int d = threadIdx.x;
    gdc_wait();                               // vaccum partials now visible
    float r = g_recip[bh];
    float s = 0;
#pragma unroll
    for (int sp = 0; sp < NSPLIT; sp++)
        s += g_partial[(bh * NSPLIT + sp) * D + d];
    out[bh * D + d] = s * r;
}

// ---------------------------------------------------------------------------
// Host: PDL chain (R9 winner).
// ---------------------------------------------------------------------------
template <typename... Args>
static void launch_pdl(void (*kern)(Args...), dim3 grid, dim3 block, Args... args)
{
    cudaLaunchConfig_t cfg = {};
    cfg.gridDim = grid;
    cfg.blockDim = block;
    cfg.dynamicSmemBytes = 0;
    cfg.stream = 0;
    cudaLaunchAttribute attr[1];
    attr[0].id = cudaLaunchAttributeProgrammaticStreamSerialization;
    attr[0].val.programmaticStreamSerializationAllowed = 1;
    cfg.attrs = attr;
    cfg.numAttrs = 1;
    cudaLaunchKernelEx(&cfg, kern, args...);
}

extern "C" void kernel_launch(void* const* d_in, const int* in_sizes, int n_in,
                              void* d_out, int out_size)
{
    const float* q           = (const float*)d_in[0];
    const int*   k_cache     = (const int*)d_in[1];
    const int*   v_cache     = (const int*)d_in[2];
    const int*   block_table = (const int*)d_in[3];
    const int*   seq_lens    = (const int*)d_in[4];
    const float* k_scale     = (const float*)d_in[5];
    const float* v_scale     = (const float*)d_in[6];
    float* out = (float*)d_out;

    rope_kernel<<<dim3(H, B), 64>>>(q, seq_lens);
    launch_pdl(score_kernel, dim3(P, H, B), dim3(256),
               k_cache, block_table, seq_lens, k_scale);
    launch_pdl(select_kernel, dim3(B * H), dim3(256),
               block_table, seq_lens, k_scale, v_scale);
    launch_pdl(vaccum_kernel, dim3(NSPLIT, H, B), dim3(256), v_cache);
    launch_pdl(combine_kernel, dim3(B * H), dim3(D), out);
}